// round 4
// baseline (speedup 1.0000x reference)
#include <cuda_runtime.h>
#include <cstdint>

#define CIN   512
#define CQK   64
#define MTOK  4096

// ---------------- scratch (device globals; no allocations) ----------------
__device__ float d_styleR[4 * CIN * MTOK];      // resized style, (B,C,M)
__device__ float d_f[4 * MTOK * CQK];           // (B,M,64)
__device__ float d_g[4 * MTOK * CQK];           // (B,M,64)
__device__ float d_hT[4 * CIN * MTOK];          // (B,C,token) for MMA B operand
__device__ float d_S[(size_t)4 * MTOK * MTOK];  // (B,M,N) logits / probs
__device__ float d_ao[4 * MTOK * CIN];          // (B,M,512)

// ---------------- packed f32x2 helpers ----------------
__device__ __forceinline__ void ffma2(unsigned long long &d, unsigned long long a, unsigned long long b) {
    asm("fma.rn.f32x2 %0, %1, %2, %0;" : "+l"(d) : "l"(a), "l"(b));
}
__device__ __forceinline__ unsigned long long bcast2(float x) {
    unsigned long long r; asm("mov.b64 %0, {%1, %1};" : "=l"(r) : "f"(x)); return r;
}
__device__ __forceinline__ float2 unpack2(unsigned long long v) {
    float2 f; asm("mov.b64 {%0, %1}, %2;" : "=f"(f.x), "=f"(f.y) : "l"(v)); return f;
}

// ---------------- tf32 helpers ----------------
__device__ __forceinline__ uint32_t tf32of(float x) {
    uint32_t r; asm("cvt.rna.tf32.f32 %0, %1;" : "=r"(r) : "f"(x)); return r;
}
__device__ __forceinline__ void split1(float x, uint32_t &h, uint32_t &l) {
    h = tf32of(x);
    l = tf32of(x - __uint_as_float(h));
}
__device__ __forceinline__ void mma_tf32(float* d, const uint4 a, const uint2 b) {
    asm("mma.sync.aligned.m16n8k8.row.col.f32.tf32.tf32.f32 "
        "{%0,%1,%2,%3}, {%4,%5,%6,%7}, {%8,%9}, {%0,%1,%2,%3};"
        : "+f"(d[0]), "+f"(d[1]), "+f"(d[2]), "+f"(d[3])
        : "r"(a.x), "r"(a.y), "r"(a.z), "r"(a.w), "r"(b.x), "r"(b.y));
}

// ============================================================================
// 1) bilinear resize style (80x80 -> 64x64), keeps channel-major (B,C,4096)
// ============================================================================
__global__ void resize_kernel(const float* __restrict__ style, float* __restrict__ out) {
    int idx = blockIdx.x * blockDim.x + threadIdx.x;
    int m  = idx & 4095;
    int bc = idx >> 12;
    int x = m & 63, y = m >> 6;
    float sx = fmaxf((x + 0.5f) * 1.25f - 0.5f, 0.0f);
    float sy = fmaxf((y + 0.5f) * 1.25f - 0.5f, 0.0f);
    int x0 = min((int)sx, 79), y0 = min((int)sy, 79);
    int x1 = min(x0 + 1, 79),  y1 = min(y0 + 1, 79);
    float wx = sx - (float)x0, wy = sy - (float)y0;
    const float* p = style + (size_t)bc * 6400;
    float a00 = p[y0 * 80 + x0], a01 = p[y0 * 80 + x1];
    float a10 = p[y1 * 80 + x0], a11 = p[y1 * 80 + x1];
    float r0 = a00 + (a01 - a00) * wx;
    float r1 = a10 + (a11 - a10) * wx;
    out[idx] = r0 + (r1 - r0) * wy;
}

// ============================================================================
// 2) projection: out[b][m][o] = sum_c X[b][c][m]*W[o][c] + bias[o]  (row-major out)
// ============================================================================
__global__ __launch_bounds__(256) void proj_kernel(
    const float* __restrict__ X, const float* __restrict__ W,
    const float* __restrict__ bias, float* __restrict__ out, int O)
{
    __shared__ float Xs[16][64];
    __shared__ float Ws[16][68];
    const int tid = threadIdx.x;
    const int b  = blockIdx.z;
    const int m0 = blockIdx.x * 64, o0 = blockIdx.y * 64;
    const float* Xb = X + (size_t)b * CIN * MTOK;

    const int oi = tid & 15;
    const int mi = tid >> 4;
    const int xr = tid >> 4, xc = (tid & 15) * 4;
    const int wo = tid >> 2, wc = (tid & 3) * 4;

    unsigned long long acc[4][2];
#pragma unroll
    for (int i = 0; i < 4; i++) { acc[i][0] = 0ull; acc[i][1] = 0ull; }

    for (int c0 = 0; c0 < CIN; c0 += 16) {
        __syncthreads();
        *(float4*)&Xs[xr][xc] = *(const float4*)&Xb[(size_t)(c0 + xr) * MTOK + m0 + xc];
        float4 wv = *(const float4*)&W[(size_t)(o0 + wo) * CIN + c0 + wc];
        Ws[wc + 0][wo] = wv.x; Ws[wc + 1][wo] = wv.y;
        Ws[wc + 2][wo] = wv.z; Ws[wc + 3][wo] = wv.w;
        __syncthreads();
#pragma unroll
        for (int c = 0; c < 16; c++) {
            ulonglong2 wp = *(const ulonglong2*)&Ws[c][oi * 4];
#pragma unroll
            for (int i = 0; i < 4; i++) {
                unsigned long long xp = bcast2(Xs[c][mi * 4 + i]);
                ffma2(acc[i][0], wp.x, xp);
                ffma2(acc[i][1], wp.y, xp);
            }
        }
    }
    float b0 = bias[o0 + oi * 4 + 0], b1 = bias[o0 + oi * 4 + 1];
    float b2 = bias[o0 + oi * 4 + 2], b3 = bias[o0 + oi * 4 + 3];
#pragma unroll
    for (int i = 0; i < 4; i++) {
        float2 u0 = unpack2(acc[i][0]);
        float2 u1 = unpack2(acc[i][1]);
        *(float4*)&out[((size_t)b * MTOK + m0 + mi * 4 + i) * O + o0 + oi * 4] =
            make_float4(u0.x + b0, u0.y + b1, u1.x + b2, u1.y + b3);
    }
}

// ============================================================================
// 2b) projection with transposed output: out[b][o][m]  (for h -> MMA B operand)
// ============================================================================
__global__ __launch_bounds__(256) void projT_kernel(
    const float* __restrict__ X, const float* __restrict__ W,
    const float* __restrict__ bias, float* __restrict__ out)
{
    __shared__ float Xs[16][64];
    __shared__ float Ws[16][68];
    const int tid = threadIdx.x;
    const int b  = blockIdx.z;
    const int m0 = blockIdx.x * 64, o0 = blockIdx.y * 64;
    const float* Xb = X + (size_t)b * CIN * MTOK;

    const int oi = tid & 15;
    const int mi = tid >> 4;
    const int xr = tid >> 4, xc = (tid & 15) * 4;
    const int wo = tid >> 2, wc = (tid & 3) * 4;

    unsigned long long acc[4][2];
#pragma unroll
    for (int i = 0; i < 4; i++) { acc[i][0] = 0ull; acc[i][1] = 0ull; }

    for (int c0 = 0; c0 < CIN; c0 += 16) {
        __syncthreads();
        *(float4*)&Xs[xr][xc] = *(const float4*)&Xb[(size_t)(c0 + xr) * MTOK + m0 + xc];
        float4 wv = *(const float4*)&W[(size_t)(o0 + wo) * CIN + c0 + wc];
        Ws[wc + 0][wo] = wv.x; Ws[wc + 1][wo] = wv.y;
        Ws[wc + 2][wo] = wv.z; Ws[wc + 3][wo] = wv.w;
        __syncthreads();
#pragma unroll
        for (int c = 0; c < 16; c++) {
            ulonglong2 wp = *(const ulonglong2*)&Ws[c][oi * 4];
#pragma unroll
            for (int i = 0; i < 4; i++) {
                unsigned long long xp = bcast2(Xs[c][mi * 4 + i]);
                ffma2(acc[i][0], wp.x, xp);
                ffma2(acc[i][1], wp.y, xp);
            }
        }
    }
    float v[4][4];
#pragma unroll
    for (int i = 0; i < 4; i++) {
        float2 u0 = unpack2(acc[i][0]);
        float2 u1 = unpack2(acc[i][1]);
        v[i][0] = u0.x; v[i][1] = u0.y; v[i][2] = u1.x; v[i][3] = u1.y;
    }
#pragma unroll
    for (int j = 0; j < 4; j++) {
        float bv = bias[o0 + oi * 4 + j];
        *(float4*)&out[((size_t)b * CIN + o0 + oi * 4 + j) * MTOK + m0 + mi * 4] =
            make_float4(v[0][j] + bv, v[1][j] + bv, v[2][j] + bv, v[3][j] + bv);
    }
}

// ============================================================================
// 3) logits: S[b][m][n] = sum_c f[b][m][c]*g[b][n][c]
// ============================================================================
__global__ __launch_bounds__(256) void logits_kernel(
    const float* __restrict__ f, const float* __restrict__ g, float* __restrict__ S)
{
    __shared__ float fs[64][68];
    __shared__ float gs[64][68];
    const int tid = threadIdx.x;
    const int b  = blockIdx.z;
    const int m0 = blockIdx.x * 64, n0 = blockIdx.y * 64;
    const float* fb = f + ((size_t)b * MTOK + m0) * CQK;
    const float* gb = g + ((size_t)b * MTOK + n0) * CQK;

#pragma unroll
    for (int kk = 0; kk < 4; kk++) {
        int idx = tid + kk * 256;
        int r = idx >> 4, c4 = (idx & 15) * 4;
        float4 fv = *(const float4*)&fb[r * CQK + c4];
        fs[c4 + 0][r] = fv.x; fs[c4 + 1][r] = fv.y; fs[c4 + 2][r] = fv.z; fs[c4 + 3][r] = fv.w;
        float4 gv = *(const float4*)&gb[r * CQK + c4];
        gs[c4 + 0][r] = gv.x; gs[c4 + 1][r] = gv.y; gs[c4 + 2][r] = gv.z; gs[c4 + 3][r] = gv.w;
    }
    __syncthreads();

    const int ni = tid & 15, mi = tid >> 4;
    unsigned long long acc[4][2];
#pragma unroll
    for (int i = 0; i < 4; i++) { acc[i][0] = 0ull; acc[i][1] = 0ull; }

#pragma unroll
    for (int c = 0; c < 64; c++) {
        ulonglong2 gp = *(const ulonglong2*)&gs[c][ni * 4];
#pragma unroll
        for (int i = 0; i < 4; i++) {
            unsigned long long fp = bcast2(fs[c][mi * 4 + i]);
            ffma2(acc[i][0], gp.x, fp);
            ffma2(acc[i][1], gp.y, fp);
        }
    }
#pragma unroll
    for (int i = 0; i < 4; i++) {
        float2 u0 = unpack2(acc[i][0]);
        float2 u1 = unpack2(acc[i][1]);
        *(float4*)&S[((size_t)(b * MTOK) + m0 + mi * 4 + i) * MTOK + n0 + ni * 4] =
            make_float4(u0.x, u0.y, u1.x, u1.y);
    }
}

// ============================================================================
// 4) row softmax over S (rows of 4096)
// ============================================================================
__global__ __launch_bounds__(256) void softmax_kernel(float* __restrict__ S) {
    float4* p = (float4*)(S + (size_t)blockIdx.x * MTOK);
    const int tid = threadIdx.x;
    float4 v[4];
#pragma unroll
    for (int k = 0; k < 4; k++) v[k] = p[tid + k * 256];

    float mx = -1e30f;
#pragma unroll
    for (int k = 0; k < 4; k++)
        mx = fmaxf(mx, fmaxf(fmaxf(v[k].x, v[k].y), fmaxf(v[k].z, v[k].w)));
#pragma unroll
    for (int off = 16; off; off >>= 1) mx = fmaxf(mx, __shfl_xor_sync(~0u, mx, off));
    __shared__ float rs[8];
    if ((tid & 31) == 0) rs[tid >> 5] = mx;
    __syncthreads();
    mx = rs[0];
#pragma unroll
    for (int k = 1; k < 8; k++) mx = fmaxf(mx, rs[k]);
    __syncthreads();

    float s = 0.0f;
#pragma unroll
    for (int k = 0; k < 4; k++) {
        v[k].x = __expf(v[k].x - mx); v[k].y = __expf(v[k].y - mx);
        v[k].z = __expf(v[k].z - mx); v[k].w = __expf(v[k].w - mx);
        s += (v[k].x + v[k].y) + (v[k].z + v[k].w);
    }
#pragma unroll
    for (int off = 16; off; off >>= 1) s += __shfl_xor_sync(~0u, s, off);
    if ((tid & 31) == 0) rs[tid >> 5] = s;
    __syncthreads();
    s = rs[0];
#pragma unroll
    for (int k = 1; k < 8; k++) s += rs[k];
    float inv = 1.0f / s;
#pragma unroll
    for (int k = 0; k < 4; k++) {
        v[k].x *= inv; v[k].y *= inv; v[k].z *= inv; v[k].w *= inv;
        p[tid + k * 256] = v[k];
    }
}

// ============================================================================
// 5) PV GEMM via mma.sync tf32 (3x decomposition):
//    ao[b][m][c] = sum_n P[b][m][n] * Ht[b][c][n]
//    CTA 128x128, 8 warps (2m x 4n), warp tile 64x32, K-chunk 32.
//    smem is fragment-major so consume side is wide LDS.
// ============================================================================
#define PV_SMEM_BYTES 65536

__global__ __launch_bounds__(256, 1) void pv_mma_kernel(
    const float* __restrict__ P, const float* __restrict__ Ht, float* __restrict__ out)
{
    extern __shared__ float sm[];
    float* Ahi = sm;
    float* Alo = sm + 4096;
    float* Bhi = sm + 8192;
    float* Blo = sm + 12288;

    const int tid = threadIdx.x, lane = tid & 31, wid = tid >> 5;
    const int wm = wid & 1, wn = wid >> 1;
    const int b  = blockIdx.z;
    const int m0 = blockIdx.x * 128, c0 = blockIdx.y * 128;
    const float* Pb = P  + ((size_t)b * MTOK + m0) * MTOK;
    const float* Hb = Ht + ((size_t)b * CIN  + c0) * MTOK;

    // staging geometry (constant across chunks)
    int aDst[4], bDst[4];
    size_t gSrc[4];
#pragma unroll
    for (int i = 0; i < 4; i++) {
        int f = tid + i * 256;          // 0..1023 float4 slots
        int row = f >> 3, c4 = f & 7;   // row 0..127, 4-float col group 0..7
        int kt = c4 >> 1;
        gSrc[i] = (size_t)row * MTOK + c4 * 4;
        int mt = row >> 4, r = row & 15;
        aDst[i] = ((kt * 8 + mt) * 32 + (r & 7) * 4) * 4 + (c4 & 1) * 2 + (r >> 3);
        int nt = row >> 3;
        bDst[i] = ((kt * 16 + nt) * 32 + (row & 7) * 4) * 2 + (c4 & 1);
    }

    float d[4][4][4];
#pragma unroll
    for (int i = 0; i < 4; i++)
#pragma unroll
        for (int j = 0; j < 4; j++)
#pragma unroll
            for (int q = 0; q < 4; q++) d[i][j][q] = 0.0f;

    float4 pA[4], pB[4];
#pragma unroll
    for (int i = 0; i < 4; i++) {
        pA[i] = *(const float4*)(Pb + gSrc[i]);
        pB[i] = *(const float4*)(Hb + gSrc[i]);
    }

    for (int kc = 0; kc < MTOK / 32; kc++) {
        __syncthreads();   // previous compute done with smem
#pragma unroll
        for (int i = 0; i < 4; i++) {
            float va[4] = {pA[i].x, pA[i].y, pA[i].z, pA[i].w};
            float vb[4] = {pB[i].x, pB[i].y, pB[i].z, pB[i].w};
#pragma unroll
            for (int e = 0; e < 4; e++) {
                uint32_t h, l;
                split1(va[e], h, l);
                Ahi[aDst[i] + e * 4] = __uint_as_float(h);
                Alo[aDst[i] + e * 4] = __uint_as_float(l);
                split1(vb[e], h, l);
                Bhi[bDst[i] + e * 2] = __uint_as_float(h);
                Blo[bDst[i] + e * 2] = __uint_as_float(l);
            }
        }
        __syncthreads();   // staging visible

        if (kc + 1 < MTOK / 32) {
            const float* Pk = Pb + (size_t)(kc + 1) * 32;
            const float* Hk = Hb + (size_t)(kc + 1) * 32;
#pragma unroll
            for (int i = 0; i < 4; i++) {
                pA[i] = *(const float4*)(Pk + gSrc[i]);
                pB[i] = *(const float4*)(Hk + gSrc[i]);
            }
        }

#pragma unroll
        for (int kt = 0; kt < 4; kt++) {
            uint4 ah[4], al[4];
            uint2 bh[4], bl[4];
#pragma unroll
            for (int i = 0; i < 4; i++) {
                int idx = ((kt * 8 + wm * 4 + i) * 32 + lane) * 4;
                ah[i] = *(const uint4*)&Ahi[idx];
                al[i] = *(const uint4*)&Alo[idx];
            }
#pragma unroll
            for (int j = 0; j < 4; j++) {
                int idx = ((kt * 16 + wn * 4 + j) * 32 + lane) * 2;
                bh[j] = *(const uint2*)&Bhi[idx];
                bl[j] = *(const uint2*)&Blo[idx];
            }
#pragma unroll
            for (int i = 0; i < 4; i++)
#pragma unroll
                for (int j = 0; j < 4; j++) {
                    mma_tf32(d[i][j], ah[i], bh[j]);
                    mma_tf32(d[i][j], ah[i], bl[j]);
                    mma_tf32(d[i][j], al[i], bh[j]);
                }
        }
    }

    // epilogue: standard m16n8 accumulator layout
    const int gr = lane >> 2, tc = lane & 3;
#pragma unroll
    for (int i = 0; i < 4; i++)
#pragma unroll
        for (int j = 0; j < 4; j++) {
            int row = m0 + wm * 64 + i * 16 + gr;
            int col = c0 + wn * 32 + j * 8 + tc * 2;
            float* o = out + ((size_t)b * MTOK + row) * CIN + col;
            *(float2*)o               = make_float2(d[i][j][0], d[i][j][1]);
            *(float2*)(o + 8 * CIN)   = make_float2(d[i][j][2], d[i][j][3]);
        }
}

// ============================================================================
// 6) final conv: out[b][o][m] = sum_c ao[b][m][c]*W[o][c] + bias[o]  (NCHW out)
// ============================================================================
__global__ __launch_bounds__(256) void projB_kernel(
    const float* __restrict__ X, const float* __restrict__ W,
    const float* __restrict__ bias, float* __restrict__ out)
{
    __shared__ float As[16][68];
    __shared__ float Ws[16][68];
    const int tid = threadIdx.x;
    const int b  = blockIdx.z;
    const int m0 = blockIdx.x * 64, o0 = blockIdx.y * 64;
    const float* Xb = X + (size_t)b * MTOK * CIN;

    const int mi = tid & 15;
    const int oi = tid >> 4;
    const int ar = tid >> 2, ac = (tid & 3) * 4;

    unsigned long long acc[4][2];
#pragma unroll
    for (int j = 0; j < 4; j++) { acc[j][0] = 0ull; acc[j][1] = 0ull; }

    for (int c0 = 0; c0 < CIN; c0 += 16) {
        __syncthreads();
        float4 xv = *(const float4*)&Xb[(size_t)(m0 + ar) * CIN + c0 + ac];
        As[ac + 0][ar] = xv.x; As[ac + 1][ar] = xv.y;
        As[ac + 2][ar] = xv.z; As[ac + 3][ar] = xv.w;
        float4 wv = *(const float4*)&W[(size_t)(o0 + ar) * CIN + c0 + ac];
        Ws[ac + 0][ar] = wv.x; Ws[ac + 1][ar] = wv.y;
        Ws[ac + 2][ar] = wv.z; Ws[ac + 3][ar] = wv.w;
        __syncthreads();
#pragma unroll
        for (int c = 0; c < 16; c++) {
            ulonglong2 mp = *(const ulonglong2*)&As[c][mi * 4];
#pragma unroll
            for (int j = 0; j < 4; j++) {
                unsigned long long wv2 = bcast2(Ws[c][oi * 4 + j]);
                ffma2(acc[j][0], mp.x, wv2);
                ffma2(acc[j][1], mp.y, wv2);
            }
        }
    }
#pragma unroll
    for (int j = 0; j < 4; j++) {
        float bv = bias[o0 + oi * 4 + j];
        float2 u0 = unpack2(acc[j][0]);
        float2 u1 = unpack2(acc[j][1]);
        *(float4*)&out[((size_t)b * CIN + o0 + oi * 4 + j) * MTOK + m0 + mi * 4] =
            make_float4(u0.x + bv, u0.y + bv, u1.x + bv, u1.y + bv);
    }
}

// ============================================================================
extern "C" void kernel_launch(void* const* d_in, const int* in_sizes, int n_in,
                              void* d_out, int out_size) {
    const float* content = (const float*)d_in[0];
    const float* style   = (const float*)d_in[1];
    const float* f_w = (const float*)d_in[2];
    const float* f_b = (const float*)d_in[3];
    const float* g_w = (const float*)d_in[4];
    const float* g_b = (const float*)d_in[5];
    const float* h_w = (const float*)d_in[6];
    const float* h_b = (const float*)d_in[7];
    const float* out_w = (const float*)d_in[8];
    const float* out_b = (const float*)d_in[9];
    float* out = (float*)d_out;

    float *styleR, *fP, *gP, *hTP, *SP, *aoP;
    cudaGetSymbolAddress((void**)&styleR, d_styleR);
    cudaGetSymbolAddress((void**)&fP, d_f);
    cudaGetSymbolAddress((void**)&gP, d_g);
    cudaGetSymbolAddress((void**)&hTP, d_hT);
    cudaGetSymbolAddress((void**)&SP, d_S);
    cudaGetSymbolAddress((void**)&aoP, d_ao);

    cudaFuncSetAttribute(pv_mma_kernel, cudaFuncAttributeMaxDynamicSharedMemorySize, PV_SMEM_BYTES);

    resize_kernel<<<(4 * CIN * MTOK) / 256, 256>>>(style, styleR);
    proj_kernel<<<dim3(64, 1, 4), 256>>>(content, f_w, f_b, fP, CQK);
    proj_kernel<<<dim3(64, 1, 4), 256>>>(styleR, g_w, g_b, gP, CQK);
    projT_kernel<<<dim3(64, 8, 4), 256>>>(styleR, h_w, h_b, hTP);
    logits_kernel<<<dim3(64, 64, 4), 256>>>(fP, gP, SP);
    softmax_kernel<<<4 * MTOK, 256>>>(SP);
    pv_mma_kernel<<<dim3(32, 4, 4), 256, PV_SMEM_BYTES>>>(SP, hTP, aoP);
    projB_kernel<<<dim3(64, 8, 4), 256>>>(aoP, out_w, out_b, out);
}

// round 5
// speedup vs baseline: 1.6092x; 1.6092x over previous
#include <cuda_runtime.h>
#include <cstdint>

#define CIN   512
#define CQK   64
#define MTOK  4096
#define NCH   (MTOK / 32)    // 128 k-chunks

// ---------------- scratch (device globals; no allocations) ----------------
__device__ float d_styleR[4 * CIN * MTOK];        // resized style, (B,C,M)
__device__ float d_f[4 * MTOK * CQK];             // (B,M,64)
__device__ float d_g[4 * MTOK * CQK];             // (B,M,64)
__device__ float d_hT[4 * CIN * MTOK];            // (B,C,token)
__device__ float d_S[(size_t)4 * MTOK * MTOK];    // (B,M,N) logits / probs
__device__ float d_Af[(size_t)4 * MTOK * MTOK];   // P in tf32 fragment-major blocks
__device__ float d_Bhi[(size_t)4 * 4 * NCH * 4096]; // H hi fragment-major
__device__ float d_Blo[(size_t)4 * 4 * NCH * 4096]; // H lo fragment-major
__device__ float d_ao[4 * MTOK * CIN];            // (B,M,512)

// ---------------- packed f32x2 helpers ----------------
__device__ __forceinline__ void ffma2(unsigned long long &d, unsigned long long a, unsigned long long b) {
    asm("fma.rn.f32x2 %0, %1, %2, %0;" : "+l"(d) : "l"(a), "l"(b));
}
__device__ __forceinline__ unsigned long long bcast2(float x) {
    unsigned long long r; asm("mov.b64 %0, {%1, %1};" : "=l"(r) : "f"(x)); return r;
}
__device__ __forceinline__ float2 unpack2(unsigned long long v) {
    float2 f; asm("mov.b64 {%0, %1}, %2;" : "=f"(f.x), "=f"(f.y) : "l"(v)); return f;
}

// ---------------- tf32 / mma / cp.async helpers ----------------
__device__ __forceinline__ uint32_t tf32of(float x) {
    uint32_t r; asm("cvt.rna.tf32.f32 %0, %1;" : "=r"(r) : "f"(x)); return r;
}
__device__ __forceinline__ void split1(float x, uint32_t &h, uint32_t &l) {
    h = tf32of(x);
    l = tf32of(x - __uint_as_float(h));
}
__device__ __forceinline__ void mma_tf32(float* d, const uint4 a, const uint2 b) {
    asm("mma.sync.aligned.m16n8k8.row.col.f32.tf32.tf32.f32 "
        "{%0,%1,%2,%3}, {%4,%5,%6,%7}, {%8,%9}, {%0,%1,%2,%3};"
        : "+f"(d[0]), "+f"(d[1]), "+f"(d[2]), "+f"(d[3])
        : "r"(a.x), "r"(a.y), "r"(a.z), "r"(a.w), "r"(b.x), "r"(b.y));
}
__device__ __forceinline__ void cp16(void* dst, const void* src) {
    unsigned s = (unsigned)__cvta_generic_to_shared(dst);
    asm volatile("cp.async.cg.shared.global [%0], [%1], 16;" :: "r"(s), "l"(src));
}
__device__ __forceinline__ void cp_commit() { asm volatile("cp.async.commit_group;"); }

// ============================================================================
// 1) bilinear resize style (80x80 -> 64x64), channel-major (B,C,4096)
// ============================================================================
__global__ void resize_kernel(const float* __restrict__ style, float* __restrict__ out) {
    int idx = blockIdx.x * blockDim.x + threadIdx.x;
    int m  = idx & 4095;
    int bc = idx >> 12;
    int x = m & 63, y = m >> 6;
    float sx = fmaxf((x + 0.5f) * 1.25f - 0.5f, 0.0f);
    float sy = fmaxf((y + 0.5f) * 1.25f - 0.5f, 0.0f);
    int x0 = min((int)sx, 79), y0 = min((int)sy, 79);
    int x1 = min(x0 + 1, 79),  y1 = min(y0 + 1, 79);
    float wx = sx - (float)x0, wy = sy - (float)y0;
    const float* p = style + (size_t)bc * 6400;
    float a00 = p[y0 * 80 + x0], a01 = p[y0 * 80 + x1];
    float a10 = p[y1 * 80 + x0], a11 = p[y1 * 80 + x1];
    float r0 = a00 + (a01 - a00) * wx;
    float r1 = a10 + (a11 - a10) * wx;
    out[idx] = r0 + (r1 - r0) * wy;
}

// ============================================================================
// 2) projection: out[b][m][o] = sum_c X[b][c][m]*W[o][c] + bias[o]
// ============================================================================
__global__ __launch_bounds__(256) void proj_kernel(
    const float* __restrict__ X, const float* __restrict__ W,
    const float* __restrict__ bias, float* __restrict__ out, int O)
{
    __shared__ float Xs[16][64];
    __shared__ float Ws[16][68];
    const int tid = threadIdx.x;
    const int b  = blockIdx.z;
    const int m0 = blockIdx.x * 64, o0 = blockIdx.y * 64;
    const float* Xb = X + (size_t)b * CIN * MTOK;

    const int oi = tid & 15;
    const int mi = tid >> 4;
    const int xr = tid >> 4, xc = (tid & 15) * 4;
    const int wo = tid >> 2, wc = (tid & 3) * 4;

    unsigned long long acc[4][2];
#pragma unroll
    for (int i = 0; i < 4; i++) { acc[i][0] = 0ull; acc[i][1] = 0ull; }

    for (int c0 = 0; c0 < CIN; c0 += 16) {
        __syncthreads();
        *(float4*)&Xs[xr][xc] = *(const float4*)&Xb[(size_t)(c0 + xr) * MTOK + m0 + xc];
        float4 wv = *(const float4*)&W[(size_t)(o0 + wo) * CIN + c0 + wc];
        Ws[wc + 0][wo] = wv.x; Ws[wc + 1][wo] = wv.y;
        Ws[wc + 2][wo] = wv.z; Ws[wc + 3][wo] = wv.w;
        __syncthreads();
#pragma unroll
        for (int c = 0; c < 16; c++) {
            ulonglong2 wp = *(const ulonglong2*)&Ws[c][oi * 4];
#pragma unroll
            for (int i = 0; i < 4; i++) {
                unsigned long long xp = bcast2(Xs[c][mi * 4 + i]);
                ffma2(acc[i][0], wp.x, xp);
                ffma2(acc[i][1], wp.y, xp);
            }
        }
    }
    float b0 = bias[o0 + oi * 4 + 0], b1 = bias[o0 + oi * 4 + 1];
    float b2 = bias[o0 + oi * 4 + 2], b3 = bias[o0 + oi * 4 + 3];
#pragma unroll
    for (int i = 0; i < 4; i++) {
        float2 u0 = unpack2(acc[i][0]);
        float2 u1 = unpack2(acc[i][1]);
        *(float4*)&out[((size_t)b * MTOK + m0 + mi * 4 + i) * O + o0 + oi * 4] =
            make_float4(u0.x + b0, u0.y + b1, u1.x + b2, u1.y + b3);
    }
}

// ============================================================================
// 2b) projection with transposed output: out[b][o][m]
// ============================================================================
__global__ __launch_bounds__(256) void projT_kernel(
    const float* __restrict__ X, const float* __restrict__ W,
    const float* __restrict__ bias, float* __restrict__ out)
{
    __shared__ float Xs[16][64];
    __shared__ float Ws[16][68];
    const int tid = threadIdx.x;
    const int b  = blockIdx.z;
    const int m0 = blockIdx.x * 64, o0 = blockIdx.y * 64;
    const float* Xb = X + (size_t)b * CIN * MTOK;

    const int oi = tid & 15;
    const int mi = tid >> 4;
    const int xr = tid >> 4, xc = (tid & 15) * 4;
    const int wo = tid >> 2, wc = (tid & 3) * 4;

    unsigned long long acc[4][2];
#pragma unroll
    for (int i = 0; i < 4; i++) { acc[i][0] = 0ull; acc[i][1] = 0ull; }

    for (int c0 = 0; c0 < CIN; c0 += 16) {
        __syncthreads();
        *(float4*)&Xs[xr][xc] = *(const float4*)&Xb[(size_t)(c0 + xr) * MTOK + m0 + xc];
        float4 wv = *(const float4*)&W[(size_t)(o0 + wo) * CIN + c0 + wc];
        Ws[wc + 0][wo] = wv.x; Ws[wc + 1][wo] = wv.y;
        Ws[wc + 2][wo] = wv.z; Ws[wc + 3][wo] = wv.w;
        __syncthreads();
#pragma unroll
        for (int c = 0; c < 16; c++) {
            ulonglong2 wp = *(const ulonglong2*)&Ws[c][oi * 4];
#pragma unroll
            for (int i = 0; i < 4; i++) {
                unsigned long long xp = bcast2(Xs[c][mi * 4 + i]);
                ffma2(acc[i][0], wp.x, xp);
                ffma2(acc[i][1], wp.y, xp);
            }
        }
    }
    float v[4][4];
#pragma unroll
    for (int i = 0; i < 4; i++) {
        float2 u0 = unpack2(acc[i][0]);
        float2 u1 = unpack2(acc[i][1]);
        v[i][0] = u0.x; v[i][1] = u0.y; v[i][2] = u1.x; v[i][3] = u1.y;
    }
#pragma unroll
    for (int j = 0; j < 4; j++) {
        float bv = bias[o0 + oi * 4 + j];
        *(float4*)&out[((size_t)b * CIN + o0 + oi * 4 + j) * MTOK + m0 + mi * 4] =
            make_float4(v[0][j] + bv, v[1][j] + bv, v[2][j] + bv, v[3][j] + bv);
    }
}

// ============================================================================
// 3) logits: S[b][m][n] = sum_c f[b][m][c]*g[b][n][c]
// ============================================================================
__global__ __launch_bounds__(256) void logits_kernel(
    const float* __restrict__ f, const float* __restrict__ g, float* __restrict__ S)
{
    __shared__ float fs[64][68];
    __shared__ float gs[64][68];
    const int tid = threadIdx.x;
    const int b  = blockIdx.z;
    const int m0 = blockIdx.x * 64, n0 = blockIdx.y * 64;
    const float* fb = f + ((size_t)b * MTOK + m0) * CQK;
    const float* gb = g + ((size_t)b * MTOK + n0) * CQK;

#pragma unroll
    for (int kk = 0; kk < 4; kk++) {
        int idx = tid + kk * 256;
        int r = idx >> 4, c4 = (idx & 15) * 4;
        float4 fv = *(const float4*)&fb[r * CQK + c4];
        fs[c4 + 0][r] = fv.x; fs[c4 + 1][r] = fv.y; fs[c4 + 2][r] = fv.z; fs[c4 + 3][r] = fv.w;
        float4 gv = *(const float4*)&gb[r * CQK + c4];
        gs[c4 + 0][r] = gv.x; gs[c4 + 1][r] = gv.y; gs[c4 + 2][r] = gv.z; gs[c4 + 3][r] = gv.w;
    }
    __syncthreads();

    const int ni = tid & 15, mi = tid >> 4;
    unsigned long long acc[4][2];
#pragma unroll
    for (int i = 0; i < 4; i++) { acc[i][0] = 0ull; acc[i][1] = 0ull; }

#pragma unroll
    for (int c = 0; c < 64; c++) {
        ulonglong2 gp = *(const ulonglong2*)&gs[c][ni * 4];
#pragma unroll
        for (int i = 0; i < 4; i++) {
            unsigned long long fp = bcast2(fs[c][mi * 4 + i]);
            ffma2(acc[i][0], gp.x, fp);
            ffma2(acc[i][1], gp.y, fp);
        }
    }
#pragma unroll
    for (int i = 0; i < 4; i++) {
        float2 u0 = unpack2(acc[i][0]);
        float2 u1 = unpack2(acc[i][1]);
        *(float4*)&S[((size_t)(b * MTOK) + m0 + mi * 4 + i) * MTOK + n0 + ni * 4] =
            make_float4(u0.x, u0.y, u1.x, u1.y);
    }
}

// ============================================================================
// 4) row softmax over S (rows of 4096)
// ============================================================================
__global__ __launch_bounds__(256) void softmax_kernel(float* __restrict__ S) {
    float4* p = (float4*)(S + (size_t)blockIdx.x * MTOK);
    const int tid = threadIdx.x;
    float4 v[4];
#pragma unroll
    for (int k = 0; k < 4; k++) v[k] = p[tid + k * 256];

    float mx = -1e30f;
#pragma unroll
    for (int k = 0; k < 4; k++)
        mx = fmaxf(mx, fmaxf(fmaxf(v[k].x, v[k].y), fmaxf(v[k].z, v[k].w)));
#pragma unroll
    for (int off = 16; off; off >>= 1) mx = fmaxf(mx, __shfl_xor_sync(~0u, mx, off));
    __shared__ float rs[8];
    if ((tid & 31) == 0) rs[tid >> 5] = mx;
    __syncthreads();
    mx = rs[0];
#pragma unroll
    for (int k = 1; k < 8; k++) mx = fmaxf(mx, rs[k]);
    __syncthreads();

    float s = 0.0f;
#pragma unroll
    for (int k = 0; k < 4; k++) {
        v[k].x = __expf(v[k].x - mx); v[k].y = __expf(v[k].y - mx);
        v[k].z = __expf(v[k].z - mx); v[k].w = __expf(v[k].w - mx);
        s += (v[k].x + v[k].y) + (v[k].z + v[k].w);
    }
#pragma unroll
    for (int off = 16; off; off >>= 1) s += __shfl_xor_sync(~0u, s, off);
    if ((tid & 31) == 0) rs[tid >> 5] = s;
    __syncthreads();
    s = rs[0];
#pragma unroll
    for (int k = 1; k < 8; k++) s += rs[k];
    float inv = 1.0f / s;
#pragma unroll
    for (int k = 0; k < 4; k++) {
        v[k].x *= inv; v[k].y *= inv; v[k].z *= inv; v[k].w *= inv;
        p[tid + k * 256] = v[k];
    }
}

// ============================================================================
// 4b) prepP: S (probs) -> tf32-rounded fragment-major blocks
//     block = (mblock 128 rows) x (kchunk 32 cols), 4096 floats contiguous.
//     slot = ((kt*8+mt)*32 + gr*4 + tc)*4 + khalf*2 + half   (A-frag layout)
// ============================================================================
__global__ __launch_bounds__(256) void prepP_kernel(
    const float* __restrict__ S, float* __restrict__ Af)
{
    __shared__ float t[4096];
    const int kc = blockIdx.x, mb = blockIdx.y, b = blockIdx.z;
    const int tid = threadIdx.x;
    const float* src = S + ((size_t)(b * MTOK) + mb * 128) * MTOK + kc * 32;

#pragma unroll
    for (int i = 0; i < 4; i++) {
        int f = tid + i * 256;            // 0..1023 float4 slots
        int row = f >> 3, c4 = f & 7;
        float4 v = *(const float4*)(src + (size_t)row * MTOK + c4 * 4);
        int kt = c4 >> 1, khalf = c4 & 1;
        int mt = row >> 4, r = row & 15, gr = r & 7, half = r >> 3;
        int base = ((kt * 8 + mt) * 32 + gr * 4) * 4 + khalf * 2 + half;
        t[base + 0]  = __uint_as_float(tf32of(v.x));
        t[base + 4]  = __uint_as_float(tf32of(v.y));
        t[base + 8]  = __uint_as_float(tf32of(v.z));
        t[base + 12] = __uint_as_float(tf32of(v.w));
    }
    __syncthreads();
    float4* dst = (float4*)(Af + (((size_t)(b * 32 + mb)) * NCH + kc) * 4096);
#pragma unroll
    for (int i = 0; i < 4; i++) {
        int f = tid + i * 256;
        dst[f] = ((const float4*)t)[f];
    }
}

// ============================================================================
// 4c) prepH: Ht -> hi/lo fragment-major blocks
//     block = (nblock 128 rows) x (kchunk 32 cols)
//     slot = ((kt*16+nt)*32 + nr*4 + tc)*2 + khalf   (B-frag layout)
// ============================================================================
__global__ __launch_bounds__(256) void prepH_kernel(
    const float* __restrict__ Ht, float* __restrict__ Bhi, float* __restrict__ Blo)
{
    __shared__ float thi[4096];
    __shared__ float tlo[4096];
    const int kc = blockIdx.x, nb = blockIdx.y, b = blockIdx.z;
    const int tid = threadIdx.x;
    const float* src = Ht + ((size_t)(b * CIN) + nb * 128) * MTOK + kc * 32;

#pragma unroll
    for (int i = 0; i < 4; i++) {
        int f = tid + i * 256;
        int row = f >> 3, c4 = f & 7;
        float4 v = *(const float4*)(src + (size_t)row * MTOK + c4 * 4);
        int kt = c4 >> 1, khalf = c4 & 1;
        int nt = row >> 3, nr = row & 7;
        int base = ((kt * 16 + nt) * 32 + nr * 4) * 2 + khalf;
        float va[4] = {v.x, v.y, v.z, v.w};
#pragma unroll
        for (int e = 0; e < 4; e++) {
            uint32_t h, l; split1(va[e], h, l);
            thi[base + e * 2] = __uint_as_float(h);
            tlo[base + e * 2] = __uint_as_float(l);
        }
    }
    __syncthreads();
    size_t blk = (((size_t)(b * 4 + nb)) * NCH + kc) * 4096;
    float4* dh = (float4*)(Bhi + blk);
    float4* dl = (float4*)(Blo + blk);
#pragma unroll
    for (int i = 0; i < 4; i++) {
        int f = tid + i * 256;
        dh[f] = ((const float4*)thi)[f];
        dl[f] = ((const float4*)tlo)[f];
    }
}

// ============================================================================
// 5) PV GEMM: pre-permuted fragments, cp.async 3-stage pipeline, 2 MMA/tile.
//    CTA 128x128, 8 warps (2m x 4n), warp tile 64x32.
// ============================================================================
#define PV_STAGE 12288                        // floats: A 4096 + Bhi 4096 + Blo 4096
#define PV_SMEM  (3 * PV_STAGE * 4)           // 147456 bytes

__global__ __launch_bounds__(256) void pv_mma_kernel(
    const float* __restrict__ Af, const float* __restrict__ Bhi,
    const float* __restrict__ Blo, float* __restrict__ out)
{
    extern __shared__ float sm[];
    const int tid = threadIdx.x, lane = tid & 31, wid = tid >> 5;
    const int wm = wid & 1, wn = wid >> 1;
    const int mb = blockIdx.x, nb = blockIdx.y, b = blockIdx.z;

    const float4* Asrc = (const float4*)(Af  + ((size_t)(b * 32 + mb)) * NCH * 4096);
    const float4* Hsrc = (const float4*)(Bhi + ((size_t)(b * 4  + nb)) * NCH * 4096);
    const float4* Lsrc = (const float4*)(Blo + ((size_t)(b * 4  + nb)) * NCH * 4096);

    auto issue = [&](int kc) {
        float* st = sm + (kc % 3) * PV_STAGE;
        const float4* a = Asrc + (size_t)kc * 1024;
        const float4* h = Hsrc + (size_t)kc * 1024;
        const float4* l = Lsrc + (size_t)kc * 1024;
#pragma unroll
        for (int i = 0; i < 4; i++) {
            int f = tid + i * 256;
            cp16((float4*)st + f,        a + f);
            cp16((float4*)(st + 4096) + f, h + f);
            cp16((float4*)(st + 8192) + f, l + f);
        }
        cp_commit();
    };

    float d[4][4][4];
#pragma unroll
    for (int i = 0; i < 4; i++)
#pragma unroll
        for (int j = 0; j < 4; j++)
#pragma unroll
            for (int q = 0; q < 4; q++) d[i][j][q] = 0.0f;

    issue(0); issue(1); issue(2);

    for (int kc = 0; kc < NCH; kc++) {
        if (kc < NCH - 2)      asm volatile("cp.async.wait_group 2;");
        else if (kc == NCH - 2) asm volatile("cp.async.wait_group 1;");
        else                    asm volatile("cp.async.wait_group 0;");
        __syncthreads();

        const float* st = sm + (kc % 3) * PV_STAGE;
        const float* A  = st;
        const float* BH = st + 4096;
        const float* BL = st + 8192;

#pragma unroll
        for (int kt = 0; kt < 4; kt++) {
            uint4 ah[4];
            uint2 bh[4], bl[4];
#pragma unroll
            for (int i = 0; i < 4; i++)
                ah[i] = *(const uint4*)(A + (((kt * 8 + wm * 4 + i) * 32 + lane) << 2));
#pragma unroll
            for (int j = 0; j < 4; j++) {
                int off = ((kt * 16 + wn * 4 + j) * 32 + lane) << 1;
                bh[j] = *(const uint2*)(BH + off);
                bl[j] = *(const uint2*)(BL + off);
            }
#pragma unroll
            for (int i = 0; i < 4; i++)
#pragma unroll
                for (int j = 0; j < 4; j++) {
                    mma_tf32(d[i][j], ah[i], bh[j]);
                    mma_tf32(d[i][j], ah[i], bl[j]);
                }
        }
        __syncthreads();
        if (kc + 3 < NCH) issue(kc + 3);
    }

    // epilogue: m16n8 accumulator layout (validated in R4)
    const int gr = lane >> 2, tc = lane & 3;
    const int m0 = mb * 128, c0 = nb * 128;
#pragma unroll
    for (int i = 0; i < 4; i++)
#pragma unroll
        for (int j = 0; j < 4; j++) {
            int row = m0 + wm * 64 + i * 16 + gr;
            int col = c0 + wn * 32 + j * 8 + tc * 2;
            float* o = out + ((size_t)b * MTOK + row) * CIN + col;
            *(float2*)o             = make_float2(d[i][j][0], d[i][j][1]);
            *(float2*)(o + 8 * CIN) = make_float2(d[i][j][2], d[i][j][3]);
        }
}

// ============================================================================
// 6) final conv: out[b][o][m] = sum_c ao[b][m][c]*W[o][c] + bias[o]  (NCHW out)
// ============================================================================
__global__ __launch_bounds__(256) void projB_kernel(
    const float* __restrict__ X, const float* __restrict__ W,
    const float* __restrict__ bias, float* __restrict__ out)
{
    __shared__ float As[16][68];
    __shared__ float Ws[16][68];
    const int tid = threadIdx.x;
    const int b  = blockIdx.z;
    const int m0 = blockIdx.x * 64, o0 = blockIdx.y * 64;
    const float* Xb = X + (size_t)b * MTOK * CIN;

    const int mi = tid & 15;
    const int oi = tid >> 4;
    const int ar = tid >> 2, ac = (tid & 3) * 4;

    unsigned long long acc[4][2];
#pragma unroll
    for (int j = 0; j < 4; j++) { acc[j][0] = 0ull; acc[j][1] = 0ull; }

    for (int c0 = 0; c0 < CIN; c0 += 16) {
        __syncthreads();
        float4 xv = *(const float4*)&Xb[(size_t)(m0 + ar) * CIN + c0 + ac];
        As[ac + 0][ar] = xv.x; As[ac + 1][ar] = xv.y;
        As[ac + 2][ar] = xv.z; As[ac + 3][ar] = xv.w;
        float4 wv = *(const float4*)&W[(size_t)(o0 + ar) * CIN + c0 + ac];
        Ws[ac + 0][ar] = wv.x; Ws[ac + 1][ar] = wv.y;
        Ws[ac + 2][ar] = wv.z; Ws[ac + 3][ar] = wv.w;
        __syncthreads();
#pragma unroll
        for (int c = 0; c < 16; c++) {
            ulonglong2 mp = *(const ulonglong2*)&As[c][mi * 4];
#pragma unroll
            for (int j = 0; j < 4; j++) {
                unsigned long long wv2 = bcast2(Ws[c][oi * 4 + j]);
                ffma2(acc[j][0], mp.x, wv2);
                ffma2(acc[j][1], mp.y, wv2);
            }
        }
    }
#pragma unroll
    for (int j = 0; j < 4; j++) {
        float bv = bias[o0 + oi * 4 + j];
        float2 u0 = unpack2(acc[j][0]);
        float2 u1 = unpack2(acc[j][1]);
        *(float4*)&out[((size_t)b * CIN + o0 + oi * 4 + j) * MTOK + m0 + mi * 4] =
            make_float4(u0.x + bv, u0.y + bv, u1.x + bv, u1.y + bv);
    }
}

// ============================================================================
extern "C" void kernel_launch(void* const* d_in, const int* in_sizes, int n_in,
                              void* d_out, int out_size) {
    const float* content = (const float*)d_in[0];
    const float* style   = (const float*)d_in[1];
    const float* f_w = (const float*)d_in[2];
    const float* f_b = (const float*)d_in[3];
    const float* g_w = (const float*)d_in[4];
    const float* g_b = (const float*)d_in[5];
    const float* h_w = (const float*)d_in[6];
    const float* h_b = (const float*)d_in[7];
    const float* out_w = (const float*)d_in[8];
    const float* out_b = (const float*)d_in[9];
    float* out = (float*)d_out;

    float *styleR, *fP, *gP, *hTP, *SP, *AfP, *BhiP, *BloP, *aoP;
    cudaGetSymbolAddress((void**)&styleR, d_styleR);
    cudaGetSymbolAddress((void**)&fP, d_f);
    cudaGetSymbolAddress((void**)&gP, d_g);
    cudaGetSymbolAddress((void**)&hTP, d_hT);
    cudaGetSymbolAddress((void**)&SP, d_S);
    cudaGetSymbolAddress((void**)&AfP, d_Af);
    cudaGetSymbolAddress((void**)&BhiP, d_Bhi);
    cudaGetSymbolAddress((void**)&BloP, d_Blo);
    cudaGetSymbolAddress((void**)&aoP, d_ao);

    cudaFuncSetAttribute(pv_mma_kernel, cudaFuncAttributeMaxDynamicSharedMemorySize, PV_SMEM);

    resize_kernel<<<(4 * CIN * MTOK) / 256, 256>>>(style, styleR);
    proj_kernel<<<dim3(64, 1, 4), 256>>>(content, f_w, f_b, fP, CQK);
    proj_kernel<<<dim3(64, 1, 4), 256>>>(styleR, g_w, g_b, gP, CQK);
    projT_kernel<<<dim3(64, 8, 4), 256>>>(styleR, h_w, h_b, hTP);
    prepH_kernel<<<dim3(NCH, 4, 4), 256>>>(hTP, BhiP, BloP);
    logits_kernel<<<dim3(64, 64, 4), 256>>>(fP, gP, SP);
    softmax_kernel<<<4 * MTOK, 256>>>(SP);
    prepP_kernel<<<dim3(NCH, 32, 4), 256>>>(SP, AfP);
    pv_mma_kernel<<<dim3(32, 4, 4), 256, PV_SMEM>>>(AfP, BhiP, BloP, out == nullptr ? nullptr : aoP);
    projB_kernel<<<dim3(64, 8, 4), 256>>>(aoP, out_w, out_b, out);
}